// round 6
// baseline (speedup 1.0000x reference)
#include <cuda_runtime.h>
#include <cuda_fp16.h>
#include <cstdint>

// Problem constants
#define BB 16
#define C 128
#define HH 64
#define WW 64
#define KK 8
#define HID 32
#define PER (128*128*9)

// ---------------- device scratch ----------------
__device__ float  g_alphas[BB*KK];
__device__ float  g_aggb[BB*C];
__device__ float  g_part[BB*C*HH];          // pool partials [b][ci][h] (raw sums over w)
__device__ __half g_aggw_h[BB*PER];         // [b][q][co][ci]
__device__ __half g_xh[(size_t)BB*66*66*128]; // padded NHWC fp16

// ---------------- PTX helpers ----------------
__device__ __forceinline__ uint32_t smem_u32(const void* p) {
    uint32_t a;
    asm("{ .reg .u64 t; cvta.to.shared.u64 t, %1; cvt.u32.u64 %0, t; }" : "=r"(a) : "l"(p));
    return a;
}
#define LDSM_X4(r0,r1,r2,r3,addr) \
    asm volatile("ldmatrix.sync.aligned.m8n8.x4.shared.b16 {%0,%1,%2,%3}, [%4];" \
        : "=r"(r0),"=r"(r1),"=r"(r2),"=r"(r3) : "r"(addr))
#define CP_ASYNC16(dst, src) \
    asm volatile("cp.async.cg.shared.global [%0], [%1], 16;" :: "r"(dst), "l"(src))
#define CP_COMMIT() asm volatile("cp.async.commit_group;" ::: "memory")
#define CP_WAIT0()  asm volatile("cp.async.wait_group 0;" ::: "memory")

__device__ __forceinline__ void mma16(float* c, const unsigned* a, unsigned b0, unsigned b1) {
    asm volatile("mma.sync.aligned.m16n8k16.row.col.f32.f16.f16.f32 "
        "{%0,%1,%2,%3}, {%4,%5,%6,%7}, {%8,%9}, {%0,%1,%2,%3};"
        : "+f"(c[0]), "+f"(c[1]), "+f"(c[2]), "+f"(c[3])
        : "r"(a[0]), "r"(a[1]), "r"(a[2]), "r"(a[3]), "r"(b0), "r"(b1));
}

// ---------------- kernel 1: NCHW fp32 -> padded NHWC fp16 + fused pool partials ----------------
// grid (64 h, 16 b), 256 threads. Thread: w = tid&63, gbase = tid>>6 (handles ci 32*gbase..+31).
// Reads: per instruction one full 128B line (32 consecutive w of one ci row). 100% coalesced.
// Writes: per thread 4 adjacent uint4 = 64B contiguous. Full sectors.
__global__ void preconv_kernel(const float* __restrict__ x) {
    __shared__ float pool[C];
    const int h = blockIdx.x, b = blockIdx.y;
    const int tid = threadIdx.x;
    const int w = tid & 63;
    const int gbase = tid >> 6;
    const int lane = tid & 31;

    if (tid < C) pool[tid] = 0.f;
    __syncthreads();

    const float* xrow = x + (((size_t)b * C) * HH + h) * WW + w;
    __half* opx = g_xh + (((size_t)(b*66 + h + 1)) * 66 + (w + 1)) * 128 + gbase * 32;

    #pragma unroll
    for (int gi = 0; gi < 4; ++gi) {
        const int g = gbase * 4 + gi;          // ci group of 8
        __half h8[8];
        #pragma unroll
        for (int k = 0; k < 8; ++k) {
            const int ci = g * 8 + k;
            float v = xrow[(size_t)ci * HH * WW];
            h8[k] = __float2half_rn(v);
            // warp-reduce over the 32 w's this warp owns (fixed ci)
            float s = v;
            #pragma unroll
            for (int o = 16; o; o >>= 1) s += __shfl_xor_sync(0xffffffffu, s, o);
            if (lane == 0) atomicAdd(&pool[ci], s);   // 2 contributors/ci: commutative -> deterministic
        }
        *reinterpret_cast<uint4*>(opx + gi * 8) = *reinterpret_cast<uint4*>(h8);
    }
    __syncthreads();
    if (tid < C) g_part[((size_t)b * C + tid) * HH + h] = pool[tid];

    // halo zeroing
    const uint4 z = {0u,0u,0u,0u};
    if (tid < 32) {
        __half* p = g_xh + ((size_t)(b*66 + h + 1) * 66 + (tid < 16 ? 0 : 65)) * 128;
        *reinterpret_cast<uint4*>(p + (tid & 15)*8) = z;
    }
    if (h == 0) {
        __half* r0 = g_xh + (size_t)(b*66 + 0)  * 66 * 128;
        __half* r1 = g_xh + (size_t)(b*66 + 65) * 66 * 128;
        for (int i = tid; i < 1056; i += 256) {
            *reinterpret_cast<uint4*>(r0 + i*8) = z;
            *reinterpret_cast<uint4*>(r1 + i*8) = z;
        }
    }
}

// ---------------- kernel 2: pool reduce + MLP + softmax ----------------
__global__ void attn_kernel(const float* __restrict__ w1, const float* __restrict__ b1,
                            const float* __restrict__ w2, const float* __restrict__ b2) {
    __shared__ float sp[BB*C];
    __shared__ float hsh[BB][HID];
    const int tid = threadIdx.x;
    for (int idx = tid; idx < BB*C; idx += 512) {
        const float4* p = reinterpret_cast<const float4*>(g_part + (size_t)idx * HH);
        float s = 0.f;
        #pragma unroll
        for (int j = 0; j < 16; ++j) {
            float4 v = p[j];
            s += (v.x + v.y) + (v.z + v.w);
        }
        sp[idx] = s * (1.f / (HH * WW));
    }
    __syncthreads();
    const int warp = tid >> 5, lane = tid & 31, b = warp;
    float acc = b1[lane];
    #pragma unroll 4
    for (int c = 0; c < C; ++c)
        acc = fmaf(sp[b*C + c], w1[lane*C + c], acc);
    hsh[b][lane] = fmaxf(acc, 0.f);
    __syncwarp();
    if (lane < KK) {
        float sc = b2[lane];
        #pragma unroll
        for (int j = 0; j < HID; ++j)
            sc = fmaf(hsh[b][j], w2[lane*HID + j], sc);
        float m = sc;
        #pragma unroll
        for (int o = 4; o; o >>= 1) m = fmaxf(m, __shfl_xor_sync(0xffu, m, o));
        float e = __expf(sc - m);
        float se = e;
        #pragma unroll
        for (int o = 4; o; o >>= 1) se += __shfl_xor_sync(0xffu, se, o);
        g_alphas[b*KK + lane] = e / se;
    }
}

// ---------------- kernel 3: aggregation -> fp16, [b][q][co][ci] ----------------
__global__ void agg_kernel(const float* __restrict__ kw, const float* __restrict__ kb) {
    __shared__ float skw[KK][1152];
    __shared__ float al[BB*KK];
    int tid = threadIdx.x;
    int co = blockIdx.x;
    if (tid < BB*KK) al[tid] = g_alphas[tid];
    for (int j = tid; j < KK*1152; j += 256) {
        int k = j / 1152, i = j - k*1152;
        skw[k][i] = kw[(size_t)k*PER + co*1152 + i];
    }
    __syncthreads();
    for (int b = 0; b < BB; ++b) {
        float a0=al[b*KK+0],a1=al[b*KK+1],a2=al[b*KK+2],a3=al[b*KK+3];
        float a4=al[b*KK+4],a5=al[b*KK+5],a6=al[b*KK+6],a7=al[b*KK+7];
        for (int i = tid; i < 1152; i += 256) {
            int q = i >> 7, ci = i & 127;
            const int src = ci*9 + q;
            float s = a0*skw[0][src] + a1*skw[1][src] + a2*skw[2][src] + a3*skw[3][src]
                    + a4*skw[4][src] + a5*skw[5][src] + a6*skw[6][src] + a7*skw[7][src];
            g_aggw_h[(size_t)((b*9 + q)*128 + co)*128 + ci] = __float2half_rn(s);
        }
    }
    if (tid < BB) {
        int b = tid;
        float s = 0.f;
        #pragma unroll
        for (int k = 0; k < KK; ++k) s = fmaf(al[b*KK + k], kb[k*C + co], s);
        g_aggb[b*C + co] = s;
    }
}

// ---------------- kernel 4: fp16 HMMA implicit conv, pipelined (unchanged) ----------------
#define W_STG  18432
#define XS_OFF (2*W_STG)
#define SMEM_TOT (XS_OFF + 4*66*144)

__global__ void __launch_bounds__(256, 2)
conv_hmma(float* __restrict__ out) {
    extern __shared__ char smem[];
    const uint32_t sb = smem_u32(smem);
    const int tid  = threadIdx.x;
    const int lane = tid & 31;
    const int wid  = tid >> 5;
    const int b    = blockIdx.y;
    const int h0   = blockIdx.x * 2;
    const int warpM = wid & 3;
    const int warpN = wid >> 2;
    const int coW   = warpM * 32;
    const int g    = lane >> 2;
    const int tig  = lane & 3;

    const __half* whb = g_aggw_h + (size_t)b * 9 * 16384;
    const __half* xhb = g_xh + (size_t)b * 66 * 66 * 128;

    const int a_corow = (lane & 7) + ((lane >> 3) & 1) * 8;
    const uint32_t a_koff = ((lane >> 4) & 1) * 16;
    const int b_px  = (lane & 7) + ((lane >> 4) & 1) * 8;
    const uint32_t b_koff = ((lane >> 3) & 1) * 16;

    float acc[2][8][4];
    #pragma unroll
    for (int mt = 0; mt < 2; ++mt)
        #pragma unroll
        for (int nt = 0; nt < 8; ++nt)
            #pragma unroll
            for (int r = 0; r < 4; ++r) acc[mt][nt][r] = 0.f;

    auto stage_w = [&](int q, int half, int buf) {
        const __half* src = whb + q * 16384 + half * 64;
        uint32_t dst = sb + (uint32_t)buf * W_STG;
        #pragma unroll
        for (int i = tid; i < 1024; i += 256) {
            int co = i >> 3, j = i & 7;
            CP_ASYNC16(dst + (uint32_t)co*144 + (uint32_t)j*16, src + co*128 + j*8);
        }
    };
    auto stage_xs = [&](int half) {
        #pragma unroll
        for (int i = tid; i < 2112; i += 256) {
            int px = i >> 3, j = i & 7;
            int xr = px / 66, col = px - xr*66;
            const __half* src = xhb + ((size_t)(h0 + xr)*66 + col)*128 + half*64 + j*8;
            CP_ASYNC16(sb + XS_OFF + (uint32_t)px*144 + (uint32_t)j*16, src);
        }
    };

    stage_xs(0);
    stage_w(0, 0, 0);
    CP_COMMIT();

    for (int s = 0; s < 18; ++s) {
        const int half = (s >= 9);
        const int q    = s - half * 9;
        const int buf  = s & 1;
        const int kh   = q / 3;
        const int kw_  = q - kh * 3;

        CP_WAIT0();
        __syncthreads();
        if (s < 17) {
            int ns = s + 1;
            int nh = (ns >= 9);
            stage_w(ns - nh * 9, nh, buf ^ 1);
            CP_COMMIT();
        }

        const uint32_t wbb = sb + (uint32_t)buf * W_STG;
        const uint32_t xrb = sb + XS_OFF + (uint32_t)((warpN + kh)*66 + kw_ + b_px)*144 + b_koff;
        const uint32_t arb = wbb + (uint32_t)(coW + a_corow)*144 + a_koff;

        #pragma unroll
        for (int ks = 0; ks < 4; ++ks) {
            unsigned a0[4], a1[4];
            LDSM_X4(a0[0], a0[1], a0[2], a0[3], arb + (uint32_t)(ks*32));
            LDSM_X4(a1[0], a1[1], a1[2], a1[3], arb + (uint32_t)(16*144 + ks*32));
            #pragma unroll
            for (int nt2 = 0; nt2 < 4; ++nt2) {
                unsigned b0, b1, b2, b3;
                LDSM_X4(b0, b1, b2, b3, xrb + (uint32_t)(nt2*16*144 + ks*32));
                mma16(acc[0][2*nt2],   a0, b0, b1);
                mma16(acc[1][2*nt2],   a1, b0, b1);
                mma16(acc[0][2*nt2+1], a0, b2, b3);
                mma16(acc[1][2*nt2+1], a1, b2, b3);
            }
        }

        if (q == 8 && half == 0) {
            __syncthreads();
            stage_xs(1);
            CP_COMMIT();
        }
    }

    const int h = h0 + warpN;
    #pragma unroll
    for (int mt = 0; mt < 2; ++mt) {
        int co = coW + mt*16 + g;
        float bias0 = g_aggb[b * C + co];
        float bias1 = g_aggb[b * C + co + 8];
        float* o0 = out + (((size_t)b * C + co) * HH + h) * WW;
        float* o1 = o0 + (size_t)8 * HH * WW;
        #pragma unroll
        for (int nt = 0; nt < 8; ++nt) {
            int cc = nt*8 + tig*2;
            float2 v0 = {acc[mt][nt][0] + bias0, acc[mt][nt][1] + bias0};
            float2 v1 = {acc[mt][nt][2] + bias1, acc[mt][nt][3] + bias1};
            *reinterpret_cast<float2*>(o0 + cc) = v0;
            *reinterpret_cast<float2*>(o1 + cc) = v1;
        }
    }
}

// ---------------- launch ----------------
extern "C" void kernel_launch(void* const* d_in, const int* in_sizes, int n_in,
                              void* d_out, int out_size) {
    const float* x  = (const float*)d_in[0];
    const float* kw = (const float*)d_in[1];
    const float* kb = (const float*)d_in[2];
    const float* w1 = (const float*)d_in[3];
    const float* b1 = (const float*)d_in[4];
    const float* w2 = (const float*)d_in[5];
    const float* b2 = (const float*)d_in[6];
    float* out = (float*)d_out;

    cudaFuncSetAttribute(conv_hmma, cudaFuncAttributeMaxDynamicSharedMemorySize, SMEM_TOT);

    preconv_kernel<<<dim3(64, 16), 256>>>(x);
    attn_kernel<<<1, 512>>>(w1, b1, w2, b2);
    agg_kernel<<<C, 256>>>(kw, kb);
    conv_hmma<<<dim3(32, 16), 256, SMEM_TOT>>>(out);
}

// round 7
// speedup vs baseline: 1.1323x; 1.1323x over previous
#include <cuda_runtime.h>
#include <cuda_fp16.h>
#include <cstdint>

// Problem constants
#define BB 16
#define C 128
#define HH 64
#define WW 64
#define KK 8
#define HID 32
#define PER (128*128*9)

// ---------------- device scratch ----------------
__device__ float  g_pooled[BB*C];
__device__ float  g_aggb[BB*C];
__device__ __half g_aggw_h[BB*PER];           // [b][q][co][ci]
__device__ __half g_xh[(size_t)BB*66*66*128]; // padded NHWC fp16

// ---------------- PTX helpers ----------------
__device__ __forceinline__ uint32_t smem_u32(const void* p) {
    uint32_t a;
    asm("{ .reg .u64 t; cvta.to.shared.u64 t, %1; cvt.u32.u64 %0, t; }" : "=r"(a) : "l"(p));
    return a;
}
#define LDSM_X4(r0,r1,r2,r3,addr) \
    asm volatile("ldmatrix.sync.aligned.m8n8.x4.shared.b16 {%0,%1,%2,%3}, [%4];" \
        : "=r"(r0),"=r"(r1),"=r"(r2),"=r"(r3) : "r"(addr))
#define CP_ASYNC16(dst, src) \
    asm volatile("cp.async.cg.shared.global [%0], [%1], 16;" :: "r"(dst), "l"(src))
#define CP_COMMIT() asm volatile("cp.async.commit_group;" ::: "memory")
#define CP_WAIT0()  asm volatile("cp.async.wait_group 0;" ::: "memory")

__device__ __forceinline__ void mma16(float* c, const unsigned* a, unsigned b0, unsigned b1) {
    asm volatile("mma.sync.aligned.m16n8k16.row.col.f32.f16.f16.f32 "
        "{%0,%1,%2,%3}, {%4,%5,%6,%7}, {%8,%9}, {%0,%1,%2,%3};"
        : "+f"(c[0]), "+f"(c[1]), "+f"(c[2]), "+f"(c[3])
        : "r"(a[0]), "r"(a[1]), "r"(a[2]), "r"(a[3]), "r"(b0), "r"(b1));
}

// ---------------- kernel 1: exact global average pool (round-1 proven) ----------------
__global__ void pool_kernel(const float* __restrict__ x) {
    int bc = blockIdx.x;
    const float4* p4 = reinterpret_cast<const float4*>(x + (size_t)bc * HH * WW);
    float s = 0.f;
    for (int i = threadIdx.x; i < HH*WW/4; i += 128) {
        float4 v = p4[i];
        s += (v.x + v.y) + (v.z + v.w);
    }
    #pragma unroll
    for (int o = 16; o; o >>= 1) s += __shfl_xor_sync(0xffffffffu, s, o);
    __shared__ float ws[4];
    if ((threadIdx.x & 31) == 0) ws[threadIdx.x >> 5] = s;
    __syncthreads();
    if (threadIdx.x == 0)
        g_pooled[bc] = (ws[0] + ws[1] + ws[2] + ws[3]) * (1.f / (HH * WW));
}

// ---------------- kernel 2: NCHW fp32 -> padded NHWC fp16 (pure convert) ----------------
// grid (64 h, 16 b), 256 threads. Phase 1: fully-coalesced float4 reads, skewed smem
// transpose (stride 200 halves + ((w>>2)&7)*8 skew). Phase 2: coalesced uint4 NHWC writes.
__global__ void preconv_kernel(const float* __restrict__ x) {
    __shared__ __half xsh[64 * 200];
    const int h = blockIdx.x, b = blockIdx.y;
    const int tid = threadIdx.x;

    #pragma unroll
    for (int it = 0; it < 8; ++it) {
        int idx = tid + it * 256;          // 0..2047
        int ci  = idx >> 4;                // 0..127
        int w4  = idx & 15;
        float4 v = *reinterpret_cast<const float4*>(
            x + ((size_t)(b*C + ci) * HH + h) * WW + w4*4);
        float fv[4] = {v.x, v.y, v.z, v.w};
        #pragma unroll
        for (int k = 0; k < 4; ++k) {
            int w = w4*4 + k;
            xsh[w*200 + ((w >> 2) & 7)*8 + ci] = __float2half_rn(fv[k]);
        }
    }
    __syncthreads();

    __half* orow = g_xh + ((size_t)(b*66 + h + 1) * 66 + 1) * 128;
    #pragma unroll
    for (int it = 0; it < 4; ++it) {
        int idx = tid + it * 256;          // 0..1023
        int w = idx >> 4, cg = idx & 15;
        uint4 vv = *reinterpret_cast<const uint4*>(&xsh[w*200 + ((w >> 2) & 7)*8 + cg*8]);
        *reinterpret_cast<uint4*>(orow + w*128 + cg*8) = vv;
    }

    // halo zeroing
    const uint4 z = {0u,0u,0u,0u};
    if (tid < 32) {
        __half* p = g_xh + ((size_t)(b*66 + h + 1) * 66 + (tid < 16 ? 0 : 65)) * 128;
        *reinterpret_cast<uint4*>(p + (tid & 15)*8) = z;
    }
    if (h == 0) {
        __half* r0 = g_xh + (size_t)(b*66 + 0)  * 66 * 128;
        __half* r1 = g_xh + (size_t)(b*66 + 65) * 66 * 128;
        for (int i = tid; i < 1056; i += 256) {
            *reinterpret_cast<uint4*>(r0 + i*8) = z;
            *reinterpret_cast<uint4*>(r1 + i*8) = z;
        }
    }
}

// ---------------- kernel 3: aggregation with INLINE attention ----------------
// Each of the 128 blocks recomputes the tiny MLP+softmax (deterministic, ~70K fma).
__global__ void agg_kernel(const float* __restrict__ kw, const float* __restrict__ kb,
                           const float* __restrict__ w1, const float* __restrict__ b1,
                           const float* __restrict__ w2, const float* __restrict__ b2) {
    __shared__ float skw[KK][1152];     // 36864 B
    __shared__ float sp[BB*C];          // 8192 B
    __shared__ float hsh[BB][HID];      // 2048 B
    __shared__ float al[BB*KK];         // 512 B
    const int tid = threadIdx.x;
    const int co = blockIdx.x;

    for (int i = tid; i < BB*C; i += 256) sp[i] = g_pooled[i];
    for (int j = tid; j < KK*1152; j += 256) {
        int k = j / 1152, i = j - k*1152;
        skw[k][i] = kw[(size_t)k*PER + co*1152 + i];
    }
    __syncthreads();

    // hidden layer: 512 entries, 2 per thread
    for (int e = tid; e < BB*HID; e += 256) {
        int b = e >> 5, j = e & 31;
        float a = b1[j];
        #pragma unroll 4
        for (int ci = 0; ci < C; ++ci)
            a = fmaf(sp[b*C + ci], w1[j*C + ci], a);
        hsh[b][j] = fmaxf(a, 0.f);
    }
    __syncthreads();

    // scores + softmax: one thread per batch
    if (tid < BB) {
        int b = tid;
        float sc[KK];
        float m = -1e30f;
        #pragma unroll
        for (int k = 0; k < KK; ++k) {
            float s = b2[k];
            #pragma unroll
            for (int j = 0; j < HID; ++j)
                s = fmaf(hsh[b][j], w2[k*HID + j], s);
            sc[k] = s;
            m = fmaxf(m, s);
        }
        float se = 0.f;
        #pragma unroll
        for (int k = 0; k < KK; ++k) { sc[k] = __expf(sc[k] - m); se += sc[k]; }
        float inv = 1.f / se;
        #pragma unroll
        for (int k = 0; k < KK; ++k) al[b*KK + k] = sc[k] * inv;
    }
    __syncthreads();

    for (int b = 0; b < BB; ++b) {
        float a0=al[b*KK+0],a1=al[b*KK+1],a2=al[b*KK+2],a3=al[b*KK+3];
        float a4=al[b*KK+4],a5=al[b*KK+5],a6=al[b*KK+6],a7=al[b*KK+7];
        for (int i = tid; i < 1152; i += 256) {
            int q = i >> 7, ci = i & 127;
            const int src = ci*9 + q;
            float s = a0*skw[0][src] + a1*skw[1][src] + a2*skw[2][src] + a3*skw[3][src]
                    + a4*skw[4][src] + a5*skw[5][src] + a6*skw[6][src] + a7*skw[7][src];
            g_aggw_h[(size_t)((b*9 + q)*128 + co)*128 + ci] = __float2half_rn(s);
        }
    }
    if (tid < BB) {
        int b = tid;
        float s = 0.f;
        #pragma unroll
        for (int k = 0; k < KK; ++k) s = fmaf(al[b*KK + k], kb[k*C + co], s);
        g_aggb[b*C + co] = s;
    }
}

// ---------------- kernel 4: fp16 HMMA implicit conv (UNCHANGED, 69.8us) ----------------
#define W_STG  18432
#define XS_OFF (2*W_STG)
#define SMEM_TOT (XS_OFF + 4*66*144)

__global__ void __launch_bounds__(256, 2)
conv_hmma(float* __restrict__ out) {
    extern __shared__ char smem[];
    const uint32_t sb = smem_u32(smem);
    const int tid  = threadIdx.x;
    const int lane = tid & 31;
    const int wid  = tid >> 5;
    const int b    = blockIdx.y;
    const int h0   = blockIdx.x * 2;
    const int warpM = wid & 3;
    const int warpN = wid >> 2;
    const int coW   = warpM * 32;
    const int g    = lane >> 2;
    const int tig  = lane & 3;

    const __half* whb = g_aggw_h + (size_t)b * 9 * 16384;
    const __half* xhb = g_xh + (size_t)b * 66 * 66 * 128;

    const int a_corow = (lane & 7) + ((lane >> 3) & 1) * 8;
    const uint32_t a_koff = ((lane >> 4) & 1) * 16;
    const int b_px  = (lane & 7) + ((lane >> 4) & 1) * 8;
    const uint32_t b_koff = ((lane >> 3) & 1) * 16;

    float acc[2][8][4];
    #pragma unroll
    for (int mt = 0; mt < 2; ++mt)
        #pragma unroll
        for (int nt = 0; nt < 8; ++nt)
            #pragma unroll
            for (int r = 0; r < 4; ++r) acc[mt][nt][r] = 0.f;

    auto stage_w = [&](int q, int half, int buf) {
        const __half* src = whb + q * 16384 + half * 64;
        uint32_t dst = sb + (uint32_t)buf * W_STG;
        #pragma unroll
        for (int i = tid; i < 1024; i += 256) {
            int co = i >> 3, j = i & 7;
            CP_ASYNC16(dst + (uint32_t)co*144 + (uint32_t)j*16, src + co*128 + j*8);
        }
    };
    auto stage_xs = [&](int half) {
        #pragma unroll
        for (int i = tid; i < 2112; i += 256) {
            int px = i >> 3, j = i & 7;
            int xr = px / 66, col = px - xr*66;
            const __half* src = xhb + ((size_t)(h0 + xr)*66 + col)*128 + half*64 + j*8;
            CP_ASYNC16(sb + XS_OFF + (uint32_t)px*144 + (uint32_t)j*16, src);
        }
    };

    stage_xs(0);
    stage_w(0, 0, 0);
    CP_COMMIT();

    for (int s = 0; s < 18; ++s) {
        const int half = (s >= 9);
        const int q    = s - half * 9;
        const int buf  = s & 1;
        const int kh   = q / 3;
        const int kw_  = q - kh * 3;

        CP_WAIT0();
        __syncthreads();
        if (s < 17) {
            int ns = s + 1;
            int nh = (ns >= 9);
            stage_w(ns - nh * 9, nh, buf ^ 1);
            CP_COMMIT();
        }

        const uint32_t wbb = sb + (uint32_t)buf * W_STG;
        const uint32_t xrb = sb + XS_OFF + (uint32_t)((warpN + kh)*66 + kw_ + b_px)*144 + b_koff;
        const uint32_t arb = wbb + (uint32_t)(coW + a_corow)*144 + a_koff;

        #pragma unroll
        for (int ks = 0; ks < 4; ++ks) {
            unsigned a0[4], a1[4];
            LDSM_X4(a0[0], a0[1], a0[2], a0[3], arb + (uint32_t)(ks*32));
            LDSM_X4(a1[0], a1[1], a1[2], a1[3], arb + (uint32_t)(16*144 + ks*32));
            #pragma unroll
            for (int nt2 = 0; nt2 < 4; ++nt2) {
                unsigned b0, b1, b2, b3;
                LDSM_X4(b0, b1, b2, b3, xrb + (uint32_t)(nt2*16*144 + ks*32));
                mma16(acc[0][2*nt2],   a0, b0, b1);
                mma16(acc[1][2*nt2],   a1, b0, b1);
                mma16(acc[0][2*nt2+1], a0, b2, b3);
                mma16(acc[1][2*nt2+1], a1, b2, b3);
            }
        }

        if (q == 8 && half == 0) {
            __syncthreads();
            stage_xs(1);
            CP_COMMIT();
        }
    }

    const int h = h0 + warpN;
    #pragma unroll
    for (int mt = 0; mt < 2; ++mt) {
        int co = coW + mt*16 + g;
        float bias0 = g_aggb[b * C + co];
        float bias1 = g_aggb[b * C + co + 8];
        float* o0 = out + (((size_t)b * C + co) * HH + h) * WW;
        float* o1 = o0 + (size_t)8 * HH * WW;
        #pragma unroll
        for (int nt = 0; nt < 8; ++nt) {
            int cc = nt*8 + tig*2;
            float2 v0 = {acc[mt][nt][0] + bias0, acc[mt][nt][1] + bias0};
            float2 v1 = {acc[mt][nt][2] + bias1, acc[mt][nt][3] + bias1};
            *reinterpret_cast<float2*>(o0 + cc) = v0;
            *reinterpret_cast<float2*>(o1 + cc) = v1;
        }
    }
}

// ---------------- launch ----------------
extern "C" void kernel_launch(void* const* d_in, const int* in_sizes, int n_in,
                              void* d_out, int out_size) {
    const float* x  = (const float*)d_in[0];
    const float* kw = (const float*)d_in[1];
    const float* kb = (const float*)d_in[2];
    const float* w1 = (const float*)d_in[3];
    const float* b1 = (const float*)d_in[4];
    const float* w2 = (const float*)d_in[5];
    const float* b2 = (const float*)d_in[6];
    float* out = (float*)d_out;

    cudaFuncSetAttribute(conv_hmma, cudaFuncAttributeMaxDynamicSharedMemorySize, SMEM_TOT);

    pool_kernel<<<BB * C, 128>>>(x);
    preconv_kernel<<<dim3(64, 16), 256>>>(x);
    agg_kernel<<<C, 256>>>(kw, kb, w1, b1, w2, b2);
    conv_hmma<<<dim3(32, 16), 256, SMEM_TOT>>>(out);
}